// round 17
// baseline (speedup 1.0000x reference)
#include <cuda_runtime.h>
#include <cstddef>
#include <cstdint>

// Problem constants
#define Bn 8
#define Tn 512
#define Nn 64
#define Hn 256   // I == H == 256

typedef unsigned long long ull;

// ---------------------------------------------------------------------------
// Scratch (device globals: allocation-free rule)
// ---------------------------------------------------------------------------
__device__ float g_xin[(size_t)Bn * Tn * Nn * Hn];   // per-layer input projections
__device__ float g_y0 [(size_t)Bn * Tn * Nn * Hn];   // layer-0 outputs

// f32x2 packed helpers -------------------------------------------------------
__device__ __forceinline__ ull dup_f32(float x) {
    ull r;
    asm("mov.b64 %0, {%1, %1};" : "=l"(r) : "f"(x));
    return r;
}
__device__ __forceinline__ void fma2(ull& acc, ull a, ull b) {
    asm("fma.rn.f32x2 %0, %1, %2, %0;" : "+l"(acc) : "l"(a), "l"(b));
}
__device__ __forceinline__ void add2(ull& acc, ull v) {
    asm("add.rn.f32x2 %0, %0, %1;" : "+l"(acc) : "l"(v));
}
__device__ __forceinline__ void unpack2(ull v, float& lo, float& hi) {
    asm("mov.b64 {%0, %1}, %2;" : "=f"(lo), "=f"(hi) : "l"(v));
}
__device__ __forceinline__ ull pack2(float lo, float hi) {
    ull r;
    asm("mov.b64 %0, {%1, %2};" : "=l"(r) : "f"(lo), "f"(hi));
    return r;
}
__device__ __forceinline__ uint32_t smem_u32(const void* p) {
    uint32_t a;
    asm("{ .reg .u64 t; cvta.to.shared.u64 t, %1; cvt.u32.u64 %0, t; }"
        : "=r"(a) : "l"(p));
    return a;
}

// ---------------------------------------------------------------------------
// Projection (f32x2, v3): reg-double-buffered X staging; jt-fastest grid.
//   64m x 64j tile, K=256. 256 threads, 2 CTAs/SM.
//   W tile loaded ONCE per block (k-major, stride 66).
//   X staged m-major stride 36 per 32-k chunk; next chunk LDG'd into regs
//   during compute of current chunk (latency hidden).
// ---------------------------------------------------------------------------
#define WSP 66   // Ws row stride (floats), k-major
#define XSP 36   // Xs row stride (floats), m-major

__global__ __launch_bounds__(256, 2) void proj_kernel(
    const float* __restrict__ Xext,
    const float* __restrict__ W,
    const float* __restrict__ bih,
    const float* __restrict__ bhh)
{
    extern __shared__ float psm[];
    float* Ws = psm;                 // [256][WSP]  Ws[k][j]
    float* Xs = psm + 256 * WSP;     // [64][XSP]   Xs[m][kc] per 32-k chunk

    const float* X = Xext ? Xext : g_y0;
    const int jt = blockIdx.x, mt = blockIdx.y, b = blockIdx.z;
    const int lin = threadIdx.x;
    const int tx = lin & 15, ty = lin >> 4;
    const int tx2 = tx * 2, ty4 = ty * 4;

    const float* Xb = X + ((size_t)b * (Tn * Nn) + mt * 64) * 256;
    const float* Wb = W + ((size_t)b * 256 + jt * 64) * 256;

    // One-time W tile load, transposed to k-major.
#pragma unroll
    for (int it = 0; it < 16; ++it) {
        int j  = ((lin >> 3) & 31) | ((it & 1) << 5);
        int kq = (lin & 7) | ((it >> 1) << 3);
        int k  = kq * 4;
        float4 wv = *(const float4*)(Wb + (size_t)j * 256 + k);
        Ws[(k + 0) * WSP + j] = wv.x;
        Ws[(k + 1) * WSP + j] = wv.y;
        Ws[(k + 2) * WSP + j] = wv.z;
        Ws[(k + 3) * WSP + j] = wv.w;
    }

    // Reg buffer for X chunk (two float4 per thread)
    const int m0s  = lin >> 3;
    const int kc0s = (lin & 7) << 2;
    const int m1s  = (lin + 256) >> 3;
    const int kc1s = ((lin + 256) & 7) << 2;
    float4 xr0 = *(const float4*)(Xb + (size_t)m0s * 256 + kc0s);
    float4 xr1 = *(const float4*)(Xb + (size_t)m1s * 256 + kc1s);

    ull a00 = 0, a01 = 0, a10 = 0, a11 = 0, a20 = 0, a21 = 0, a30 = 0, a31 = 0;

    for (int kk = 0; kk < 256; kk += 32) {
        __syncthreads();   // Xs free (prev compute done); also orders W STS once
        *(float4*)(Xs + m0s * XSP + kc0s) = xr0;
        *(float4*)(Xs + m1s * XSP + kc1s) = xr1;
        __syncthreads();
        if (kk < 224) {    // prefetch next chunk; latency hides under compute
            xr0 = *(const float4*)(Xb + (size_t)m0s * 256 + kk + 32 + kc0s);
            xr1 = *(const float4*)(Xb + (size_t)m1s * 256 + kk + 32 + kc1s);
        }

#pragma unroll
        for (int q = 0; q < 8; ++q) {
            float4 xv0 = *(const float4*)(Xs + (ty4 + 0) * XSP + 4 * q);
            float4 xv1 = *(const float4*)(Xs + (ty4 + 1) * XSP + 4 * q);
            float4 xv2 = *(const float4*)(Xs + (ty4 + 2) * XSP + 4 * q);
            float4 xv3 = *(const float4*)(Xs + (ty4 + 3) * XSP + 4 * q);
            const float* wrow = Ws + (size_t)(kk + 4 * q) * WSP;
#pragma unroll
            for (int dk = 0; dk < 4; ++dk) {
                ull w0 = *(const ull*)(wrow + dk * WSP + tx2);
                ull w1 = *(const ull*)(wrow + dk * WSP + tx2 + 32);
                float c0 = dk == 0 ? xv0.x : dk == 1 ? xv0.y : dk == 2 ? xv0.z : xv0.w;
                float c1 = dk == 0 ? xv1.x : dk == 1 ? xv1.y : dk == 2 ? xv1.z : xv1.w;
                float c2 = dk == 0 ? xv2.x : dk == 1 ? xv2.y : dk == 2 ? xv2.z : xv2.w;
                float c3 = dk == 0 ? xv3.x : dk == 1 ? xv3.y : dk == 2 ? xv3.z : xv3.w;
                ull d0 = dup_f32(c0), d1 = dup_f32(c1);
                ull d2 = dup_f32(c2), d3 = dup_f32(c3);
                fma2(a00, d0, w0); fma2(a01, d0, w1);
                fma2(a10, d1, w0); fma2(a11, d1, w1);
                fma2(a20, d2, w0); fma2(a21, d2, w1);
                fma2(a30, d3, w0); fma2(a31, d3, w1);
            }
        }
    }

    // Epilogue: add bias, store float2 pairs (coalesced per warp)
    const int j0 = jt * 64 + tx2, j1 = j0 + 32;
    float2 bi0 = *(const float2*)(bih + b * 256 + j0);
    float2 bh0 = *(const float2*)(bhh + b * 256 + j0);
    float2 bi1 = *(const float2*)(bih + b * 256 + j1);
    float2 bh1 = *(const float2*)(bhh + b * 256 + j1);
    const float b00 = bi0.x + bh0.x, b01 = bi0.y + bh0.y;
    const float b10 = bi1.x + bh1.x, b11 = bi1.y + bh1.y;

    const size_t mbase = (size_t)b * (Tn * Nn) + mt * 64 + ty4;
    ull accs[4][2] = {{a00, a01}, {a10, a11}, {a20, a21}, {a30, a31}};
#pragma unroll
    for (int i = 0; i < 4; ++i) {
        float lo, hi;
        unpack2(accs[i][0], lo, hi);
        *(float2*)(g_xin + (mbase + i) * 256 + j0) = make_float2(lo + b00, hi + b01);
        unpack2(accs[i][1], lo, hi);
        *(float2*)(g_xin + (mbase + i) * 256 + j1) = make_float2(lo + b10, hi + b11);
    }
}

// ---------------------------------------------------------------------------
// Recurrence v2: mbarrier sync hidden under own-half compute; split epilogue.
//   64 clusters of 2 CTAs. Cluster = (instance b, n-octet). CTA = j-half.
//   Threads whose k-half == own CTA's j-rows start each step's GEMM with only
//   a local __syncthreads; peer-half threads try_wait (acquire.cluster) on an
//   mbarrier signalled by both CTAs at end of previous step. Epilogue split:
//   kh0 owns j{0,1} of each quad, kh1 owns j{2,3}.
// ---------------------------------------------------------------------------
#define WP 132   // w_s row stride (floats)
#define HP 10    // h_buf row stride (floats)

__global__ __launch_bounds__(256) __cluster_dims__(2, 1, 1)
void rec_kernel(
    const float* __restrict__ hx,     // [B, L, N, H]
    const float* __restrict__ whh,    // [B, H, H]
    float* __restrict__ yext,         // layer outputs (nullptr -> g_y0)
    float* __restrict__ hn,           // [B, L, N, H] final hidden
    int layer)
{
    extern __shared__ float sm[];
    float* w_s  = sm;                       // [256][WP]  k-major, j-half fast
    float* hbuf = sm + 256 * WP;            // [2][256][HP] k = GLOBAL j index
    ull* red  = (ull*)(sm + 256 * WP + 2 * 256 * HP);  // redA[128][2], redB[128][2]
    ull* mbar = red + 512;                  // 1 mbarrier (8 B)

    const int jh  = blockIdx.x;             // j-half = cluster rank (0/1)
    const int bn  = blockIdx.y;             // b*8 + n-octet
    const int b   = bn >> 3, nch = bn & 7;
    const int lin = threadIdx.x;
    const int kh  = lin >> 7;               // k-half (warp-uniform)
    const int wl  = lin & 127;
    const int jc  = wl >> 5;                // j-chunk of 32 within half (0..3)
    const int lane = wl & 31;
    const int q   = lane & 7;               // j-quad (0..7)
    const int p   = lane >> 3;              // n-pair (0..3)
    const int jl  = jc * 32 + q * 4;        // j within half (0..124)
    const int p2  = p * 2;
    const int kbeg = kh << 7;
    const bool own = (kh == jh);            // this k-half produced by own CTA

    float* y = yext ? yext : g_y0;

    const uint32_t mbar_l = smem_u32(mbar);
    if (lin == 0) {
        asm volatile("mbarrier.init.shared.b64 [%0], %1;"
                     :: "r"(mbar_l), "r"(2u) : "memory");
    }

    // Resident W half, transposed k-major: w_s[k][j] = whh[b][jh*128+j][k]
    const float* wb = whh + ((size_t)b * 256 + jh * 128) * 256;
    for (int f = lin; f < 8192; f += 256) {       // 128 j x 64 float4
        int j = f >> 6, kc = (f & 63) << 2;
        float4 v = *(const float4*)(wb + (size_t)j * 256 + kc);
        w_s[(kc + 0) * WP + j] = v.x;
        w_s[(kc + 1) * WP + j] = v.y;
        w_s[(kc + 2) * WP + j] = v.z;
        w_s[(kc + 3) * WP + j] = v.w;
    }

    // t=0 h staging: full 256-k rows for our 8 n, transposed into hbuf[1]
    const float* h0 = hx + (size_t)(b * 2 + layer) * Nn * Hn + (size_t)nch * 8 * Hn;
    for (int f = lin; f < 2048; f += 256) {       // 8 n x 256 k scalars
        int n = f >> 8, k = f & 255;
        hbuf[(size_t)(256 + k) * HP + n] = h0[n * 256 + k];   // buffer 1
    }
    __syncthreads();
    // Cluster-wide: mbar init visible before any remote arrive
    asm volatile("barrier.cluster.arrive.aligned;" ::: "memory");
    asm volatile("barrier.cluster.wait.aligned;"   ::: "memory");

    // Peer DSMEM addresses
    uint32_t hbuf_peer, mbar_r;
    {
        const uint32_t hbuf_local = smem_u32(hbuf);
        asm("mapa.shared::cluster.u32 %0, %1, %2;"
            : "=r"(hbuf_peer) : "r"(hbuf_local), "r"(jh ^ 1));
        asm("mapa.shared::cluster.u32 %0, %1, %2;"
            : "=r"(mbar_r) : "r"(mbar_l), "r"(jh ^ 1));
    }

    // Epilogue ownership: kh0 -> j pair {jl, jl+1}; kh1 -> {jl+2, jl+3}
    const int jE    = jl + kh * 2;
    const int jrowE = jh * 128 + jE;
    const size_t xyE = (size_t)nch * 8 * Hn + jrowE;

    for (int t = 0; t < Tn; ++t) {
        // Prefetch xin[t] fragment (issued before any wait)
        const size_t tb = ((size_t)b * Tn + t) * (Nn * Hn) + xyE;
        float2 x0 = __ldg((const float2*)(g_xin + tb + (size_t)(p2 + 0) * Hn));
        float2 x1 = __ldg((const float2*)(g_xin + tb + (size_t)(p2 + 1) * Hn));

        // Peer-half warps wait for previous step's phase; own-half proceed.
        if (t > 0 && !own) {
            const uint32_t par = (uint32_t)((t - 1) & 1);
            uint32_t done = 0;
            while (!done) {
                asm volatile(
                    "{\n\t.reg .pred p;\n\t"
                    "mbarrier.try_wait.parity.acquire.cluster.shared::cta.b64 p, [%1], %2;\n\t"
                    "selp.b32 %0, 1, 0, p;\n\t}"
                    : "=r"(done) : "r"(mbar_l), "r"(par) : "memory");
            }
        }

        const float* hcur = hbuf + (size_t)(((t + 1) & 1) * 256) * HP;

        // Packed-f32x2 mainloop over this thread's k-half
        ull a00 = 0ull, a01 = 0ull, a10 = 0ull, a11 = 0ull;
#pragma unroll 8
        for (int k = kbeg; k < kbeg + 128; ++k) {
            float2 hv = *(const float2*)(hcur + (size_t)k * HP + p2);
            ulonglong2 wv = *(const ulonglong2*)(w_s + (size_t)k * WP + jl);
            ull h0d = dup_f32(hv.x);
            ull h1d = dup_f32(hv.y);
            fma2(a00, h0d, wv.x);
            fma2(a01, h0d, wv.y);
            fma2(a10, h1d, wv.x);
            fma2(a11, h1d, wv.y);
        }

        // Cross-half exchange: each half exports its NON-owned j pair
        if (kh == 0) {
            *(ulonglong2*)(red + (size_t)wl * 2) = make_ulonglong2(a01, a11);
        } else {
            *(ulonglong2*)(red + 256 + (size_t)wl * 2) = make_ulonglong2(a00, a10);
        }
        __syncthreads();

        ull m0, m1;
        if (kh == 0) {
            ulonglong2 o = *(const ulonglong2*)(red + 256 + (size_t)wl * 2);
            m0 = a00; add2(m0, o.x);
            m1 = a10; add2(m1, o.y);
        } else {
            ulonglong2 o = *(const ulonglong2*)(red + (size_t)wl * 2);
            m0 = a01; add2(m0, o.x);
            m1 = a11; add2(m1, o.y);
        }

        float e0l, e0h, e1l, e1h;
        unpack2(m0, e0l, e0h);
        unpack2(m1, e1l, e1h);
        float2 v0 = make_float2(tanhf(e0l + x0.x), tanhf(e0h + x0.y));
        float2 v1 = make_float2(tanhf(e1l + x1.x), tanhf(e1h + x1.y));

        // y (and hn) global stores
        float* yt = y + ((size_t)b * Tn + t) * (Nn * Hn) + xyE;
        *(float2*)(yt + (size_t)(p2 + 0) * Hn) = v0;
        *(float2*)(yt + (size_t)(p2 + 1) * Hn) = v1;
        if (t == Tn - 1) {
            float* hnp = hn + (size_t)(b * 2 + layer) * Nn * Hn + xyE;
            *(float2*)(hnp + (size_t)(p2 + 0) * Hn) = v0;
            *(float2*)(hnp + (size_t)(p2 + 1) * Hn) = v1;
        }

        // h stores: local + peer DSMEM, rows = global j, cols = local n-pair
        const int boff = (t & 1) * 256;
        float* hl = hbuf + (size_t)(boff + jrowE) * HP + p2;
        const uint32_t rbase = hbuf_peer
            + (uint32_t)(((boff + jrowE) * HP + p2) * sizeof(float));
        *(float2*)(hl + 0 * HP) = make_float2(v0.x, v1.x);
        *(float2*)(hl + 1 * HP) = make_float2(v0.y, v1.y);
        ull pk0 = pack2(v0.x, v1.x);
        ull pk1 = pack2(v0.y, v1.y);
        asm volatile("st.shared::cluster.b64 [%0], %1;"
                     :: "r"(rbase + 0 * HP * 4), "l"(pk0) : "memory");
        asm volatile("st.shared::cluster.b64 [%0], %1;"
                     :: "r"(rbase + 1 * HP * 4), "l"(pk1) : "memory");

        __syncthreads();   // all stores of this CTA ordered before the arrive
        if (lin == 0) {
            asm volatile("mbarrier.arrive.release.cluster.shared::cta.b64 _, [%0];"
                         :: "r"(mbar_l) : "memory");
            asm volatile("mbarrier.arrive.release.cluster.shared::cluster.b64 _, [%0];"
                         :: "r"(mbar_r) : "memory");
        }
    }

    // Keep both CTAs alive until all in-flight DSMEM stores landed
    asm volatile("barrier.cluster.arrive.aligned;" ::: "memory");
    asm volatile("barrier.cluster.wait.aligned;"   ::: "memory");
}

// ---------------------------------------------------------------------------
// Launch: 4 launches total (proj, rec) x 2 layers
// ---------------------------------------------------------------------------
extern "C" void kernel_launch(void* const* d_in, const int* in_sizes, int n_in,
                              void* d_out, int out_size)
{
    const float* x    = (const float*)d_in[0];
    const float* hx   = (const float*)d_in[1];
    const float* wih0 = (const float*)d_in[2];
    const float* whh0 = (const float*)d_in[3];
    const float* bih0 = (const float*)d_in[4];
    const float* bhh0 = (const float*)d_in[5];
    const float* wih1 = (const float*)d_in[6];
    const float* whh1 = (const float*)d_in[7];
    const float* bih1 = (const float*)d_in[8];
    const float* bhh1 = (const float*)d_in[9];

    float* out = (float*)d_out;                          // [B, T, N, H]
    float* hn  = out + (size_t)Bn * Tn * Nn * Hn;        // [B, L, N, H]

    // proj: Ws[256][66] + Xs[64][36]
    const size_t proj_smem = (size_t)(256 * WSP + 64 * XSP) * sizeof(float); // 76800
    cudaFuncSetAttribute(proj_kernel, cudaFuncAttributeMaxDynamicSharedMemorySize,
                         (int)proj_smem);

    // rec: w_s + hbuf + red (512 ull) + mbar (8B, pad to 16)
    const size_t rec_smem = (size_t)(256 * WP + 2 * 256 * HP) * sizeof(float)
                          + 512 * sizeof(ull) + 16;
    cudaFuncSetAttribute(rec_kernel, cudaFuncAttributeMaxDynamicSharedMemorySize,
                         (int)rec_smem);

    dim3 pgrid(Hn / 64, Tn * Nn / 64, Bn);   // (4 jt, 512 mt, 8 b) — jt fastest
    dim3 rgrid(2, Bn * 8);                    // 128 CTAs = 64 clusters of 2

    // Layer 0
    proj_kernel<<<pgrid, 256, proj_smem>>>(x, wih0, bih0, bhh0);
    rec_kernel<<<rgrid, 256, rec_smem>>>(hx, whh0, nullptr, hn, 0);

    // Layer 1
    proj_kernel<<<pgrid, 256, proj_smem>>>(nullptr, wih1, bih1, bhh1);
    rec_kernel<<<rgrid, 256, rec_smem>>>(hx, whh1, out, hn, 1);
}